// round 12
// baseline (speedup 1.0000x reference)
#include <cuda_runtime.h>
#include <cstdint>

#define BATCH 16
#define CCH   512
#define HWSZ  1024
#define NHEAD 4
#define HDIM  128
#define NGRP  32
#define CPG   16
#define EPSV  1e-5f

// ======================= PTX helpers ========================================
__device__ __forceinline__ uint32_t smem_to_u32(const void* p) {
    uint32_t a;
    asm("{ .reg .u64 t; cvta.to.shared.u64 t, %1; cvt.u32.u64 %0, t; }"
        : "=r"(a) : "l"(p));
    return a;
}
__device__ __forceinline__ void cp16(uint32_t dst, const void* src) {
    asm volatile("cp.async.cg.shared.global [%0], [%1], 16;"
                 :: "r"(dst), "l"(src));
}
#define CP_COMMIT() asm volatile("cp.async.commit_group;" ::: "memory")
#define CP_WAIT(n)  asm volatile("cp.async.wait_group %0;" :: "n"(n) : "memory")
#define GROUP_BAR(id) asm volatile("bar.sync %0, 256;" :: "r"(id) : "memory")

__device__ __forceinline__ void ldsm4(uint32_t* r, uint32_t addr) {
    asm volatile("ldmatrix.sync.aligned.m8n8.x4.shared.b16 {%0,%1,%2,%3}, [%4];"
                 : "=r"(r[0]), "=r"(r[1]), "=r"(r[2]), "=r"(r[3]) : "r"(addr));
}
__device__ __forceinline__ void mma_tf32(float* c, const uint32_t* a,
                                         uint32_t b0, uint32_t b1) {
    asm volatile(
        "mma.sync.aligned.m16n8k8.row.col.f32.tf32.tf32.f32 "
        "{%0,%1,%2,%3}, {%4,%5,%6,%7}, {%8,%9}, {%0,%1,%2,%3};"
        : "+f"(c[0]), "+f"(c[1]), "+f"(c[2]), "+f"(c[3])
        : "r"(a[0]), "r"(a[1]), "r"(a[2]), "r"(a[3]), "r"(b0), "r"(b1));
}
__device__ __forceinline__ float to_tf32(float x) {
    uint32_t u;
    asm("cvt.rna.tf32.f32 %0, %1;" : "=r"(u) : "f"(x));
    return __uint_as_float(u);
}

// ========================= scratch (static) ================================
__device__ float g_stats[BATCH * NGRP * 2];
__device__ float g_hnT[BATCH * HWSZ * CCH];              // tf32 [b][p][c]
__device__ float g_w  [4 * CCH * CCH];                   // tf32 weights [o][c]
__device__ float g_q  [BATCH * NHEAD * HWSZ * HDIM];     // [bh][p][d]
__device__ float g_k  [BATCH * NHEAD * HWSZ * HDIM];     // [bh][p][d]
__device__ float g_v  [BATCH * NHEAD * HDIM * HWSZ];     // [bh][d][p]
__device__ float g_ao [BATCH * HWSZ * CCH];              // tf32 [b][p][c]

// ========================= GroupNorm stats =================================
__global__ __launch_bounds__(256)
void gn_stats(const float* __restrict__ x, float* __restrict__ stats)
{
    int bid = blockIdx.x;
    size_t base = (size_t)bid * (CPG * HWSZ);
    const float4* xb4 = (const float4*)(x + base);
    int t = threadIdx.x;

    float s = 0.f, ss = 0.f;
    for (int i = t; i < 4096; i += 256) {
        float4 v = xb4[i];
        s  += v.x + v.y + v.z + v.w;
        ss += v.x*v.x + v.y*v.y + v.z*v.z + v.w*v.w;
    }
    __shared__ float rs[8], rss[8];
    int lane = t & 31, wid = t >> 5;
    #pragma unroll
    for (int o = 16; o; o >>= 1) {
        s  += __shfl_xor_sync(~0u, s, o);
        ss += __shfl_xor_sync(~0u, ss, o);
    }
    if (lane == 0) { rs[wid] = s; rss[wid] = ss; }
    __syncthreads();
    if (t == 0) {
        float ts = 0.f, tss = 0.f;
        #pragma unroll
        for (int i = 0; i < 8; ++i) { ts += rs[i]; tss += rss[i]; }
        float mean = ts * (1.f / 16384.f);
        float var  = tss * (1.f / 16384.f) - mean * mean;
        stats[bid * 2]     = mean;
        stats[bid * 2 + 1] = rsqrtf(var + EPSV);
    }
}

// ============ fused normalize + transpose + tf32: x -> hnT =================
__global__ __launch_bounds__(256)
void t_norm_kernel(const float* __restrict__ x, const float* __restrict__ stats,
                   const float* __restrict__ gamma, const float* __restrict__ beta,
                   float* __restrict__ T)
{
    __shared__ float tl[32][33];
    int p0 = blockIdx.x * 32, c0 = blockIdx.y * 32, b = blockIdx.z;
    int tx = threadIdx.x, ty = threadIdx.y;
    #pragma unroll
    for (int j = 0; j < 4; ++j)
        tl[ty + 8*j][tx] = x[((size_t)b*CCH + c0 + ty + 8*j) * HWSZ + p0 + tx];
    __syncthreads();
    int c = c0 + tx;
    int g = c >> 4;
    float mean = stats[(b * 32 + g) * 2];
    float inv  = stats[(b * 32 + g) * 2 + 1];
    float gm = gamma[c] * inv;
    float bt = beta[c] - mean * gm;
    #pragma unroll
    for (int j = 0; j < 4; ++j) {
        size_t o = ((size_t)b*HWSZ + p0 + ty + 8*j) * CCH + c;
        T[o] = to_tf32(tl[tx][ty + 8*j] * gm + bt);
    }
}

// ==================== weight tf32 round =====================================
__global__ __launch_bounds__(256)
void wconv_kernel(const float* __restrict__ W0, const float* __restrict__ W1,
                  const float* __restrict__ W2, const float* __restrict__ W3,
                  float* __restrict__ Wo)
{
    const float* W = blockIdx.y == 0 ? W0 : blockIdx.y == 1 ? W1 :
                     blockIdx.y == 2 ? W2 : W3;
    size_t i = (size_t)blockIdx.x * 256 + threadIdx.x;
    Wo[(size_t)blockIdx.y * (CCH * CCH) + i] = to_tf32(W[i]);
}

// ============ TF32 conv GEMM: CTA 128x256, 8 warps of 64x64, 3-stage =======
// D[128 m][256 n] = sum_K A[m][K]*B[n][K]. A,B K-major tf32-rounded fp32.
// Warp grid 2(M)x4(N); warp tile 64x64 -> 0.125 B/MAC smem traffic.
// Epilogue staged via smem in two 128-col halves.
#define TSTRIDE  144
#define ATILE_B  (128 * TSTRIDE)     // 18432
#define BTILE_B  (256 * TSTRIDE)     // 36864
#define STG      (ATILE_B + BTILE_B) // 55296
#define SMEM_GEMM (3 * STG)          // 165888

__device__ __forceinline__ void load_chunk_t(
    const float* __restrict__ Ab, const float* __restrict__ Bb,
    int K, int m0, int n0, int kc, uint32_t bufb, int t)
{
    #pragma unroll
    for (int it = 0; it < 4; ++it) {
        int idx = t + it * 256;           // A: 128 rows x 8 segs
        int r = idx >> 3, sg = (idx & 7) * 16;
        cp16(bufb + (uint32_t)r * TSTRIDE + sg,
             (const char*)(Ab + (size_t)(m0 + r) * K + kc) + sg);
    }
    #pragma unroll
    for (int it = 0; it < 8; ++it) {
        int idx = t + it * 256;           // B: 256 rows x 8 segs
        int r = idx >> 3, sg = (idx & 7) * 16;
        cp16(bufb + ATILE_B + (uint32_t)r * TSTRIDE + sg,
             (const char*)(Bb + (size_t)(n0 + r) * K + kc) + sg);
    }
}

template <int MODE>
__global__ __launch_bounds__(256, 1)
void gemm_tf(const float* __restrict__ A, long long A_bs,
             const float* __restrict__ B, long long B_bs,
             int K, const float* __restrict__ bias,
             const float* __restrict__ resid, float* __restrict__ O)
{
    extern __shared__ char smem[];
    uint32_t sbase = smem_to_u32(smem);
    int t = threadIdx.x;
    int wid = t >> 5, lane = t & 31;
    int m0 = blockIdx.y * 128, n0 = blockIdx.x * 256, z = blockIdx.z;

    const float* Ab = A + (long long)z * A_bs;
    const float* Bb = B + (long long)z * B_bs;

    int wm = wid & 1;       // M offset wm*64
    int wn = wid >> 1;      // N offset wn*64

    uint32_t aOff = (uint32_t)(wm * 64 + (lane & 7) + ((lane >> 3) & 1) * 8)
                    * TSTRIDE + ((lane >> 4) & 1) * 16;
    uint32_t bOff = (uint32_t)(wn * 64 + (lane & 7) + ((lane >> 4) & 1) * 8)
                    * TSTRIDE + ((lane >> 3) & 1) * 16 + ATILE_B;

    float acc[4][8][4];
    #pragma unroll
    for (int i = 0; i < 4; ++i)
        #pragma unroll
        for (int j = 0; j < 8; ++j)
            #pragma unroll
            for (int c = 0; c < 4; ++c) acc[i][j][c] = 0.f;

    const int NC = K >> 5;

    load_chunk_t(Ab, Bb, K, m0, n0, 0, sbase, t);
    CP_COMMIT();
    load_chunk_t(Ab, Bb, K, m0, n0, 32, sbase + STG, t);
    CP_COMMIT();

    for (int i = 0; i < NC; ++i) {
        if (i + 1 < NC) { CP_WAIT(1); } else { CP_WAIT(0); }
        __syncthreads();
        if (i + 2 < NC) {
            load_chunk_t(Ab, Bb, K, m0, n0, (i + 2) * 32,
                         sbase + ((i + 2) % 3) * STG, t);
            CP_COMMIT();
        }

        uint32_t base = sbase + (i % 3) * STG;
        #pragma unroll
        for (int kst = 0; kst < 4; ++kst) {
            uint32_t ko = kst * 32;
            uint32_t af[4][4];
            #pragma unroll
            for (int mt = 0; mt < 4; ++mt)
                ldsm4(af[mt], base + aOff + mt * (16 * TSTRIDE) + ko);
            #pragma unroll
            for (int np = 0; np < 4; ++np) {
                uint32_t bb[4];
                ldsm4(bb, base + bOff + np * (16 * TSTRIDE) + ko);
                #pragma unroll
                for (int mt = 0; mt < 4; ++mt) {
                    mma_tf32(acc[mt][2*np    ], af[mt], bb[0], bb[1]);
                    mma_tf32(acc[mt][2*np + 1], af[mt], bb[2], bb[3]);
                }
            }
        }
    }
    __syncthreads();   // all compute done before epilogue overwrites buffers

    // ---- epilogue: two 128-col halves through smem [128][132] ----
    float* st = (float*)smem;
    #pragma unroll
    for (int h = 0; h < 2; ++h) {
        if ((wn >> 1) == h) {
            #pragma unroll
            for (int mt = 0; mt < 4; ++mt) {
                int r = wm * 64 + mt * 16 + (lane >> 2);
                #pragma unroll
                for (int nt = 0; nt < 8; ++nt) {
                    int cl = (wn & 1) * 64 + nt * 8 + (lane & 3) * 2;
                    const float* a = acc[mt][nt];
                    if (MODE == 4) {      // transposed staging st[n][m]
                        st[(cl    ) * 132 + r    ] = a[0];
                        st[(cl + 1) * 132 + r    ] = a[1];
                        st[(cl    ) * 132 + r + 8] = a[2];
                        st[(cl + 1) * 132 + r + 8] = a[3];
                    } else {              // st[m][n]
                        st[(r    ) * 132 + cl    ] = a[0];
                        st[(r    ) * 132 + cl + 1] = a[1];
                        st[(r + 8) * 132 + cl    ] = a[2];
                        st[(r + 8) * 132 + cl + 1] = a[3];
                    }
                }
            }
        }
        __syncthreads();

        int n0h = n0 + h * 128;
        if (MODE == 4) {
            for (int idx = t; idx < 4096; idx += 256) {
                int n = idx >> 5, m4 = (idx & 31) * 4;
                size_t a = (size_t)z * 524288 + (size_t)(n0h + n) * 1024 + m0 + m4;
                float bv = __ldg(bias + n0h + n);
                float4 v = *(const float4*)(st + n * 132 + m4);
                float4 rr = *(const float4*)(resid + a);
                v.x += bv + rr.x; v.y += bv + rr.y;
                v.z += bv + rr.z; v.w += bv + rr.w;
                *(float4*)(O + a) = v;
            }
        } else {
            for (int idx = t; idx < 4096; idx += 256) {
                int m = idx >> 5, c4 = (idx & 31) * 4;
                float4 v = *(const float4*)(st + m * 132 + c4);
                size_t off;
                if (MODE == 0) {
                    v.x += __ldg(bias + n0h + c4);
                    v.y += __ldg(bias + n0h + c4 + 1);
                    v.z += __ldg(bias + n0h + c4 + 2);
                    v.w += __ldg(bias + n0h + c4 + 3);
                    off = (size_t)z * 524288 + (size_t)n0h * 1024
                        + (size_t)(m0 + m) * 128 + c4;
                } else { // MODE 1
                    float bv = __ldg(bias + m0 + m);
                    v.x += bv; v.y += bv; v.z += bv; v.w += bv;
                    off = (size_t)z * 524288 + (size_t)(m0 + m) * 1024 + n0h + c4;
                }
                v.x = to_tf32(v.x); v.y = to_tf32(v.y);
                v.z = to_tf32(v.z); v.w = to_tf32(v.w);
                *(float4*)(O + off) = v;
            }
        }
        __syncthreads();
    }
}

// ==================== fused flash attention (dual-group) ====================
// block = (q-tile 128, bh), 512 thr / 16 warps, 2 groups of 8 warps.
// Group g owns q rows [g*64, g*64+64); groups share double-buffered K,V.
// Swizzled smem: addr = (row*STRIDE + byteCol) ^ ((row&7)<<4).
#define QS_O 0                        // Q: 128 x 512B swizzled
#define KS_O 65536                    // K: 2 bufs x 64 x 512B
#define VS_O 131072                   // V: 2 bufs x 128 x 256B
#define PS_O 196608                   // P: 2 groups x 64 x 256B
#define PBUF 16384
#define AL_O 229376                   // alpha[128]
#define LI_O 229888                   // 1/l [128]
#define SMEM_FLASH 230400

__global__ __launch_bounds__(512, 1)
void flash_kernel(const float* __restrict__ Q, const float* __restrict__ K,
                  const float* __restrict__ V, float* __restrict__ AO)
{
    extern __shared__ char smem[];
    uint32_t sb = smem_to_u32(smem);
    int t = threadIdx.x;
    int wid = t >> 5, lane = t & 31;
    int q0 = blockIdx.x * 128;
    int bh = blockIdx.y;
    const char* Qg = (const char*)(Q + (size_t)bh * 131072);
    const char* Kg = (const char*)(K + (size_t)bh * 131072);
    const char* Vg = (const char*)(V + (size_t)bh * 131072);

    int g = wid >> 3, w = wid & 7;
    int wql = (w & 1) * 32;
    int wkl = (w >> 1) * 16;
    int wdl = (w >> 1) * 32;

    #pragma unroll
    for (int it = 0; it < 8; ++it) {
        int idx = t + it * 512;
        int r = idx >> 5, sg = (idx & 31) * 16;
        cp16(sb + QS_O + (((uint32_t)r * 512 + sg) ^ ((r & 7) << 4)),
             Qg + (size_t)(q0 + r) * 512 + sg);
    }
    #pragma unroll
    for (int it = 0; it < 4; ++it) {
        int idx = t + it * 512;
        int r = idx >> 5, sg = (idx & 31) * 16;
        cp16(sb + KS_O + (((uint32_t)r * 512 + sg) ^ ((r & 7) << 4)),
             Kg + (size_t)r * 512 + sg);
        int rv = idx >> 4, sgv = (idx & 15) * 16;
        cp16(sb + VS_O + (((uint32_t)rv * 256 + sgv) ^ ((rv & 7) << 4)),
             Vg + (size_t)rv * 4096 + sgv);
    }
    CP_COMMIT();

    uint32_t rx = (uint32_t)(lane & 7) << 4;
    int arow = (lane & 7) + ((lane >> 3) & 1) * 8;
    int aseg = ((lane >> 4) & 1) * 16;
    int brow = (lane & 7) + ((lane >> 4) & 1) * 8;
    int bseg = ((lane >> 3) & 1) * 16;
    uint32_t aQ = sb + QS_O + (uint32_t)(g * 64 + wql + arow) * 512 + aseg;
    uint32_t bK = (uint32_t)(wkl + brow) * 512 + bseg;
    uint32_t aP = sb + PS_O + g * PBUF + (uint32_t)(wql + arow) * 256 + aseg;
    uint32_t bV = (uint32_t)(wdl + brow) * 256 + bseg;

    float oacc[2][4][4];
    #pragma unroll
    for (int i = 0; i < 2; ++i)
        #pragma unroll
        for (int j = 0; j < 4; ++j)
            #pragma unroll
            for (int c = 0; c < 4; ++c) oacc[i][j][c] = 0.f;

    float m_run = -1e30f, l_run = 0.f;
    float* al = (float*)(smem + AL_O);
    float* li = (float*)(smem + LI_O);
    int r_loc = (t & 255) >> 2;
    int qd = t & 3;
    int gr = t >> 2;
    const float scale = 0.08838834764831844f;

    for (int i = 0; i < 16; ++i) {
        __syncthreads();
        if (i + 1 < 16) {
            uint32_t kb = sb + KS_O + ((i + 1) & 1) * 32768;
            uint32_t vb = sb + VS_O + ((i + 1) & 1) * 32768;
            #pragma unroll
            for (int it = 0; it < 4; ++it) {
                int idx = t + it * 512;
                int r = idx >> 5, sg = (idx & 31) * 16;
                cp16(kb + (((uint32_t)r * 512 + sg) ^ ((r & 7) << 4)),
                     Kg + (size_t)((i + 1) * 64 + r) * 512 + sg);
                int rv = idx >> 4, sgv = (idx & 15) * 16;
                cp16(vb + (((uint32_t)rv * 256 + sgv) ^ ((rv & 7) << 4)),
                     Vg + (size_t)rv * 4096 + (size_t)(i + 1) * 256 + sgv);
            }
            CP_COMMIT();
            CP_WAIT(1);
        } else {
            CP_WAIT(0);
        }
        __syncthreads();

        float sacc[2][2][4];
        #pragma unroll
        for (int a = 0; a < 2; ++a)
            #pragma unroll
            for (int b = 0; b < 2; ++b)
                #pragma unroll
                for (int c = 0; c < 4; ++c) sacc[a][b][c] = 0.f;

        uint32_t kb = sb + KS_O + (i & 1) * 32768 + bK;
        #pragma unroll
        for (int d8 = 0; d8 < 16; ++d8) {
            uint32_t ko = d8 * 32;
            uint32_t a0[4], a1[4], bb[4];
            ldsm4(a0, (aQ + ko) ^ rx);
            ldsm4(a1, (aQ + 16 * 512 + ko) ^ rx);
            ldsm4(bb, (kb + ko) ^ rx);
            mma_tf32(sacc[0][0], a0, bb[0], bb[1]);
            mma_tf32(sacc[0][1], a0, bb[2], bb[3]);
            mma_tf32(sacc[1][0], a1, bb[0], bb[1]);
            mma_tf32(sacc[1][1], a1, bb[2], bb[3]);
        }

        {
            int lr2 = lane >> 2, lc2 = (lane & 3) * 2;
            #pragma unroll
            for (int mt = 0; mt < 2; ++mt) {
                int rr = wql + mt * 16 + lr2;
                uint32_t rxs = ((uint32_t)(rr & 7) << 4);
                #pragma unroll
                for (int nt = 0; nt < 2; ++nt) {
                    int cc = wkl + nt * 8 + lc2;
                    uint32_t o0 = ((uint32_t)(PS_O + g * PBUF + rr * 256 + cc * 4)) ^ rxs;
                    uint32_t o1 = ((uint32_t)(PS_O + g * PBUF + (rr + 8) * 256 + cc * 4)) ^ rxs;
                    *(float2*)(smem + o0) = make_float2(sacc[mt][nt][0], sacc[mt][nt][1]);
                    *(float2*)(smem + o1) = make_float2(sacc[mt][nt][2], sacc[mt][nt][3]);
                }
            }
        }
        GROUP_BAR(g + 1);

        {
            uint32_t rxs = ((uint32_t)(r_loc & 7) << 4);
            uint32_t pbase = (uint32_t)(PS_O + g * PBUF + r_loc * 256 + qd * 64);
            float4 vv[4];
            float mx = -1e30f;
            #pragma unroll
            for (int j = 0; j < 4; ++j) {
                vv[j] = *(float4*)(smem + ((pbase + j * 16) ^ rxs));
                vv[j].x *= scale; vv[j].y *= scale;
                vv[j].z *= scale; vv[j].w *= scale;
                mx = fmaxf(mx, fmaxf(fmaxf(vv[j].x, vv[j].y),
                                     fmaxf(vv[j].z, vv[j].w)));
            }
            mx = fmaxf(mx, __shfl_xor_sync(~0u, mx, 1));
            mx = fmaxf(mx, __shfl_xor_sync(~0u, mx, 2));
            float m_new = fmaxf(m_run, mx);
            float sum = 0.f;
            #pragma unroll
            for (int j = 0; j < 4; ++j) {
                float4 e;
                e.x = __expf(vv[j].x - m_new); e.y = __expf(vv[j].y - m_new);
                e.z = __expf(vv[j].z - m_new); e.w = __expf(vv[j].w - m_new);
                sum += e.x + e.y + e.z + e.w;
                e.x = to_tf32(e.x); e.y = to_tf32(e.y);
                e.z = to_tf32(e.z); e.w = to_tf32(e.w);
                *(float4*)(smem + ((pbase + j * 16) ^ rxs)) = e;
            }
            sum += __shfl_xor_sync(~0u, sum, 1);
            sum += __shfl_xor_sync(~0u, sum, 2);
            float alpha = __expf(m_run - m_new);
            l_run = l_run * alpha + sum;
            m_run = m_new;
            if (qd == 0) al[gr] = alpha;
        }
        GROUP_BAR(g + 1);

        #pragma unroll
        for (int mt = 0; mt < 2; ++mt) {
            int rr = wql + mt * 16 + (lane >> 2);
            float a0 = al[g * 64 + rr], a1 = al[g * 64 + rr + 8];
            #pragma unroll
            for (int nt = 0; nt < 4; ++nt) {
                oacc[mt][nt][0] *= a0; oacc[mt][nt][1] *= a0;
                oacc[mt][nt][2] *= a1; oacc[mt][nt][3] *= a1;
            }
        }
        uint32_t vb = sb + VS_O + (i & 1) * 32768 + bV;
        #pragma unroll
        for (int k8 = 0; k8 < 8; ++k8) {
            uint32_t ko = k8 * 32;
            uint32_t a0[4], a1[4];
            ldsm4(a0, (aP + ko) ^ rx);
            ldsm4(a1, (aP + 16 * 256 + ko) ^ rx);
            #pragma unroll
            for (int np = 0; np < 2; ++np) {
                uint32_t bb[4];
                ldsm4(bb, (vb + np * 16 * 256 + ko) ^ rx);
                mma_tf32(oacc[0][2*np    ], a0, bb[0], bb[1]);
                mma_tf32(oacc[0][2*np + 1], a0, bb[2], bb[3]);
                mma_tf32(oacc[1][2*np    ], a1, bb[0], bb[1]);
                mma_tf32(oacc[1][2*np + 1], a1, bb[2], bb[3]);
            }
        }
    }

    if (qd == 0) li[gr] = 1.f / l_run;
    __syncthreads();

    float* st = (float*)smem;
    #pragma unroll
    for (int mt = 0; mt < 2; ++mt) {
        int rr = wql + mt * 16 + (lane >> 2);
        int grr = g * 64 + rr;
        float li0 = li[grr], li1 = li[grr + 8];
        #pragma unroll
        for (int nt = 0; nt < 4; ++nt) {
            int cc = wdl + nt * 8 + (lane & 3) * 2;
            st[grr * 132 + cc]           = oacc[mt][nt][0] * li0;
            st[grr * 132 + cc + 1]       = oacc[mt][nt][1] * li0;
            st[(grr + 8) * 132 + cc]     = oacc[mt][nt][2] * li1;
            st[(grr + 8) * 132 + cc + 1] = oacc[mt][nt][3] * li1;
        }
    }
    __syncthreads();

    float* aob = AO + (size_t)(bh >> 2) * 524288 + (size_t)(bh & 3) * 128;
    for (int idx = t; idx < 4096; idx += 512) {
        int m = idx >> 5, c4 = (idx & 31) * 4;
        float4 v = *(const float4*)(st + m * 132 + c4);
        v.x = to_tf32(v.x); v.y = to_tf32(v.y);
        v.z = to_tf32(v.z); v.w = to_tf32(v.w);
        *(float4*)(aob + (size_t)(q0 + m) * 512 + c4) = v;
    }
}

// ==================== launch ================================================
extern "C" void kernel_launch(void* const* d_in, const int* in_sizes, int n_in,
                              void* d_out, int out_size)
{
    const float* x     = (const float*)d_in[0];
    const float* gamma = (const float*)d_in[1];
    const float* beta  = (const float*)d_in[2];
    const float* wq    = (const float*)d_in[3];
    const float* bq    = (const float*)d_in[4];
    const float* wk    = (const float*)d_in[5];
    const float* bk    = (const float*)d_in[6];
    const float* wv    = (const float*)d_in[7];
    const float* bv    = (const float*)d_in[8];
    const float* wp    = (const float*)d_in[9];
    const float* bp    = (const float*)d_in[10];
    float* out = (float*)d_out;

    float *stats, *hnT, *W, *q, *k, *v, *ao;
    cudaGetSymbolAddress((void**)&stats, g_stats);
    cudaGetSymbolAddress((void**)&hnT, g_hnT);
    cudaGetSymbolAddress((void**)&W,   g_w);
    cudaGetSymbolAddress((void**)&q,   g_q);
    cudaGetSymbolAddress((void**)&k,   g_k);
    cudaGetSymbolAddress((void**)&v,   g_v);
    cudaGetSymbolAddress((void**)&ao,  g_ao);

    cudaFuncSetAttribute(gemm_tf<0>, cudaFuncAttributeMaxDynamicSharedMemorySize, SMEM_GEMM);
    cudaFuncSetAttribute(gemm_tf<1>, cudaFuncAttributeMaxDynamicSharedMemorySize, SMEM_GEMM);
    cudaFuncSetAttribute(gemm_tf<4>, cudaFuncAttributeMaxDynamicSharedMemorySize, SMEM_GEMM);
    cudaFuncSetAttribute(flash_kernel, cudaFuncAttributeMaxDynamicSharedMemorySize, SMEM_FLASH);

    gn_stats<<<BATCH * NGRP, 256>>>(x, stats);
    t_norm_kernel<<<dim3(32, 16, BATCH), dim3(32, 8)>>>(x, stats, gamma, beta, hnT);
    wconv_kernel<<<dim3(1024, 4), 256>>>(wq, wk, wv, wp, W);

    const long long HNB = (long long)HWSZ * CCH;     // 524288
    const long long WS  = (long long)CCH * CCH;      // 262144

    // Q, K: M=p(128-tiles of 1024), N=o(256-tiles of 512)
    gemm_tf<0><<<dim3(2, 8, BATCH), 256, SMEM_GEMM>>>(
        hnT, HNB, W + 0 * WS, 0, CCH, bq, nullptr, q);
    gemm_tf<0><<<dim3(2, 8, BATCH), 256, SMEM_GEMM>>>(
        hnT, HNB, W + 1 * WS, 0, CCH, bk, nullptr, k);
    // V: M=o(128-tiles of 512), N=p(256-tiles of 1024)
    gemm_tf<1><<<dim3(4, 4, BATCH), 256, SMEM_GEMM>>>(
        W + 2 * WS, 0, hnT, HNB, CCH, bv, nullptr, v);
    // fused attention -> ao [b][p][c]
    flash_kernel<<<dim3(8, 64), 512, SMEM_FLASH>>>(q, k, v, ao);
    // proj + bias + residual -> out [b][o][p]
    gemm_tf<4><<<dim3(2, 8, BATCH), 256, SMEM_GEMM>>>(
        ao, HNB, W + 3 * WS, 0, CCH, bp, x, out);
}

// round 14
// speedup vs baseline: 1.0524x; 1.0524x over previous
#include <cuda_runtime.h>
#include <cstdint>

#define BATCH 16
#define CCH   512
#define HWSZ  1024
#define NHEAD 4
#define HDIM  128
#define NGRP  32
#define CPG   16
#define EPSV  1e-5f

// ======================= PTX helpers ========================================
__device__ __forceinline__ uint32_t smem_to_u32(const void* p) {
    uint32_t a;
    asm("{ .reg .u64 t; cvta.to.shared.u64 t, %1; cvt.u32.u64 %0, t; }"
        : "=r"(a) : "l"(p));
    return a;
}
__device__ __forceinline__ void cp16(uint32_t dst, const void* src) {
    asm volatile("cp.async.cg.shared.global [%0], [%1], 16;"
                 :: "r"(dst), "l"(src));
}
#define CP_COMMIT() asm volatile("cp.async.commit_group;" ::: "memory")
#define CP_WAIT(n)  asm volatile("cp.async.wait_group %0;" :: "n"(n) : "memory")
#define GROUP_BAR(id) asm volatile("bar.sync %0, 256;" :: "r"(id) : "memory")

__device__ __forceinline__ void ldsm4(uint32_t* r, uint32_t addr) {
    asm volatile("ldmatrix.sync.aligned.m8n8.x4.shared.b16 {%0,%1,%2,%3}, [%4];"
                 : "=r"(r[0]), "=r"(r[1]), "=r"(r[2]), "=r"(r[3]) : "r"(addr));
}
__device__ __forceinline__ void mma_tf32(float* c, const uint32_t* a,
                                         uint32_t b0, uint32_t b1) {
    asm volatile(
        "mma.sync.aligned.m16n8k8.row.col.f32.tf32.tf32.f32 "
        "{%0,%1,%2,%3}, {%4,%5,%6,%7}, {%8,%9}, {%0,%1,%2,%3};"
        : "+f"(c[0]), "+f"(c[1]), "+f"(c[2]), "+f"(c[3])
        : "r"(a[0]), "r"(a[1]), "r"(a[2]), "r"(a[3]), "r"(b0), "r"(b1));
}
__device__ __forceinline__ float to_tf32(float x) {
    uint32_t u;
    asm("cvt.rna.tf32.f32 %0, %1;" : "=r"(u) : "f"(x));
    return __uint_as_float(u);
}

// ========================= scratch (static) ================================
__device__ float g_hnT[BATCH * HWSZ * CCH];              // tf32 [b][p][c]
__device__ float g_w  [4 * CCH * CCH];                   // tf32 weights [o][c]
__device__ float g_q  [BATCH * NHEAD * HWSZ * HDIM];     // [bh][p][d]
__device__ float g_k  [BATCH * NHEAD * HWSZ * HDIM];     // [bh][p][d]
__device__ float g_v  [BATCH * NHEAD * HDIM * HWSZ];     // [bh][d][p]
__device__ float g_ao [BATCH * HWSZ * CCH];              // tf32 [b][p][c]

// ======== fused GroupNorm: stats + normalize + transpose + tf32 ============
// block = (b, g): 16 ch x 1024 px group in 64KB smem. 512 threads.
// Output: hnT [b][p][c] tf32-rounded.
#define GN_SMEM (65536 + 512)
__global__ __launch_bounds__(512)
void gn_fused(const float* __restrict__ x, const float* __restrict__ gamma,
              const float* __restrict__ beta, float* __restrict__ T)
{
    extern __shared__ float sm[];
    float* tile = sm;                 // [16][1024]
    float* red  = sm + 16384;
    int bid = blockIdx.x;             // b*32 + g
    int b = bid >> 5, g = bid & 31;
    int t = threadIdx.x;

    const float4* src = (const float4*)(x + (size_t)bid * 16384);
    float4* tile4 = (float4*)tile;
    float s = 0.f, ss = 0.f;
    #pragma unroll
    for (int i = 0; i < 8; ++i) {
        int idx = t + i * 512;
        float4 v = src[idx];
        tile4[idx] = v;
        s  += v.x + v.y + v.z + v.w;
        ss += v.x*v.x + v.y*v.y + v.z*v.z + v.w*v.w;
    }
    int lane = t & 31, wid = t >> 5;
    #pragma unroll
    for (int o = 16; o; o >>= 1) {
        s  += __shfl_xor_sync(~0u, s, o);
        ss += __shfl_xor_sync(~0u, ss, o);
    }
    if (lane == 0) { red[wid] = s; red[16 + wid] = ss; }
    __syncthreads();
    if (t == 0) {
        float ts = 0.f, tss = 0.f;
        #pragma unroll
        for (int i = 0; i < 16; ++i) { ts += red[i]; tss += red[16 + i]; }
        float mean = ts * (1.f / 16384.f);
        float var  = tss * (1.f / 16384.f) - mean * mean;
        red[32] = mean;
        red[33] = rsqrtf(var + EPSV);
    }
    __syncthreads();
    if (t < 16) {
        float mean = red[32], inv = red[33];
        float gm = gamma[g * 16 + t] * inv;
        red[34 + t] = gm;
        red[50 + t] = beta[g * 16 + t] - mean * gm;
    }
    __syncthreads();

    #pragma unroll
    for (int rep = 0; rep < 2; ++rep) {
        int p = t + rep * 512;
        float4 o[4];
        float* op = (float*)o;
        #pragma unroll
        for (int c = 0; c < 16; ++c)
            op[c] = to_tf32(tile[c * 1024 + p] * red[34 + c] + red[50 + c]);
        float4* dst = (float4*)(T + ((size_t)b * 1024 + p) * 512 + g * 16);
        dst[0] = o[0]; dst[1] = o[1]; dst[2] = o[2]; dst[3] = o[3];
    }
}

// ==================== weight tf32 round =====================================
__global__ __launch_bounds__(256)
void wconv_kernel(const float* __restrict__ W0, const float* __restrict__ W1,
                  const float* __restrict__ W2, const float* __restrict__ W3,
                  float* __restrict__ Wo)
{
    const float* W = blockIdx.y == 0 ? W0 : blockIdx.y == 1 ? W1 :
                     blockIdx.y == 2 ? W2 : W3;
    size_t i = (size_t)blockIdx.x * 256 + threadIdx.x;
    Wo[(size_t)blockIdx.y * (CCH * CCH) + i] = to_tf32(W[i]);
}

// ==================== TF32 conv GEMM, 3-stage (R11 shape) ==================
// D[128 m][128 n] = sum_K A[m][K]*B[n][K]. 8 warps 4(M)x2(N), warp 32x64.
// Modes:
//  1: v conv   — M=o, N=p; +bias[m]; tf32 out [bh][d][p]
//  4: proj     — M=p, N=o; +bias[n]+resid; fp32 out [b][o][p]
//  5: qk conv  — M=p, N=o in [0,1024): n<512 -> Q (+bias), else K (+bias2)
#define TSTRIDE  144
#define TILE_T   18432
#define STAGE_T  (2 * TILE_T)
#define SMEM_GEMM (3 * STAGE_T)      // 110592

__device__ __forceinline__ void load_chunk_t(
    const float* __restrict__ Ab, const float* __restrict__ Bb,
    int K, int m0, int n0, int kc, uint32_t bufb, int t)
{
    #pragma unroll
    for (int it = 0; it < 4; ++it) {
        int idx = t + it * 256;
        int r   = idx >> 3;
        int sg  = (idx & 7) * 16;
        uint32_t so = (uint32_t)r * TSTRIDE + sg;
        cp16(bufb + so, (const char*)(Ab + (size_t)(m0 + r) * K + kc) + sg);
        cp16(bufb + TILE_T + so, (const char*)(Bb + (size_t)(n0 + r) * K + kc) + sg);
    }
}

template <int MODE>
__global__ __launch_bounds__(256, 2)
void gemm_tf(const float* __restrict__ A, long long A_bs,
             const float* __restrict__ B, long long B_bs,
             int K, const float* __restrict__ bias,
             const float* __restrict__ bias2,
             const float* __restrict__ resid,
             float* __restrict__ O, float* __restrict__ O2)
{
    extern __shared__ char smem[];
    uint32_t sbase = smem_to_u32(smem);
    int t = threadIdx.x;
    int wid = t >> 5, lane = t & 31;
    int m0 = blockIdx.y * 128, n0 = blockIdx.x * 128, z = blockIdx.z;

    const float* Ab = A + (long long)z * A_bs;
    const float* Bb = B + (long long)z * B_bs;

    int wm = wid & 3;
    int wn = wid >> 2;

    uint32_t aOff = (uint32_t)(wm * 32 + (lane & 7) + ((lane >> 3) & 1) * 8)
                    * TSTRIDE + ((lane >> 4) & 1) * 16;
    uint32_t bOff = (uint32_t)(wn * 64 + (lane & 7) + ((lane >> 4) & 1) * 8)
                    * TSTRIDE + ((lane >> 3) & 1) * 16 + TILE_T;

    float acc[2][8][4];
    #pragma unroll
    for (int i = 0; i < 2; ++i)
        #pragma unroll
        for (int j = 0; j < 8; ++j)
            #pragma unroll
            for (int c = 0; c < 4; ++c) acc[i][j][c] = 0.f;

    const int NC = K >> 5;

    load_chunk_t(Ab, Bb, K, m0, n0, 0, sbase, t);
    CP_COMMIT();
    load_chunk_t(Ab, Bb, K, m0, n0, 32, sbase + STAGE_T, t);
    CP_COMMIT();

    for (int i = 0; i < NC; ++i) {
        if (i + 1 < NC) { CP_WAIT(1); } else { CP_WAIT(0); }
        __syncthreads();
        if (i + 2 < NC) {
            load_chunk_t(Ab, Bb, K, m0, n0, (i + 2) * 32,
                         sbase + ((i + 2) % 3) * STAGE_T, t);
            CP_COMMIT();
        }

        uint32_t base = sbase + (i % 3) * STAGE_T;
        #pragma unroll
        for (int kst = 0; kst < 4; ++kst) {
            uint32_t ko = kst * 32;
            uint32_t a0[4], a1[4];
            ldsm4(a0, base + aOff + ko);
            ldsm4(a1, base + aOff + 16 * TSTRIDE + ko);
            #pragma unroll
            for (int np = 0; np < 4; ++np) {
                uint32_t bb[4];
                ldsm4(bb, base + bOff + np * 16 * TSTRIDE + ko);
                mma_tf32(acc[0][2*np    ], a0, bb[0], bb[1]);
                mma_tf32(acc[0][2*np + 1], a0, bb[2], bb[3]);
                mma_tf32(acc[1][2*np    ], a1, bb[0], bb[1]);
                mma_tf32(acc[1][2*np + 1], a1, bb[2], bb[3]);
            }
        }
    }
    __syncthreads();

    float* st = (float*)smem;
    #pragma unroll
    for (int mt = 0; mt < 2; ++mt) {
        int r = wm * 32 + mt * 16 + (lane >> 2);
        #pragma unroll
        for (int nt = 0; nt < 8; ++nt) {
            int c = wn * 64 + nt * 8 + (lane & 3) * 2;
            const float* a = acc[mt][nt];
            if (MODE == 4) {
                st[(c    ) * 132 + r    ] = a[0];
                st[(c + 1) * 132 + r    ] = a[1];
                st[(c    ) * 132 + r + 8] = a[2];
                st[(c + 1) * 132 + r + 8] = a[3];
            } else {
                st[(r    ) * 132 + c    ] = a[0];
                st[(r    ) * 132 + c + 1] = a[1];
                st[(r + 8) * 132 + c    ] = a[2];
                st[(r + 8) * 132 + c + 1] = a[3];
            }
        }
    }
    __syncthreads();

    if (MODE == 4) {
        for (int idx = t; idx < 4096; idx += 256) {
            int n = idx >> 5, m4 = (idx & 31) * 4;
            size_t a = (size_t)z * 524288 + (size_t)(n0 + n) * 1024 + m0 + m4;
            float bv = __ldg(bias + n0 + n);
            float4 v = *(const float4*)(st + n * 132 + m4);
            float4 rr = *(const float4*)(resid + a);
            v.x += bv + rr.x; v.y += bv + rr.y;
            v.z += bv + rr.z; v.w += bv + rr.w;
            *(float4*)(O + a) = v;
        }
    } else {
        const float* bs = bias;
        float* Od = O;
        int nn0 = n0;
        if (MODE == 5 && n0 >= 512) { bs = bias2; Od = O2; nn0 = n0 - 512; }
        for (int idx = t; idx < 4096; idx += 256) {
            int m = idx >> 5, c4 = (idx & 31) * 4;
            float4 v = *(const float4*)(st + m * 132 + c4);
            size_t off;
            if (MODE == 5) {
                v.x += __ldg(bs + nn0 + c4);
                v.y += __ldg(bs + nn0 + c4 + 1);
                v.z += __ldg(bs + nn0 + c4 + 2);
                v.w += __ldg(bs + nn0 + c4 + 3);
                off = (size_t)z * 524288 + (size_t)nn0 * 1024
                    + (size_t)(m0 + m) * 128 + c4;
            } else { // MODE 1
                float bv = __ldg(bias + m0 + m);
                v.x += bv; v.y += bv; v.z += bv; v.w += bv;
                off = (size_t)z * 524288 + (size_t)(m0 + m) * 1024 + n0 + c4;
            }
            v.x = to_tf32(v.x); v.y = to_tf32(v.y);
            v.z = to_tf32(v.z); v.w = to_tf32(v.w);
            *(float4*)(Od + off) = v;
        }
    }
}

// ==================== fused flash attention (dual-group) ====================
#define QS_O 0                        // Q: 128 x 512B swizzled
#define KS_O 65536                    // K: 2 bufs x 64 x 512B
#define VS_O 131072                   // V: 2 bufs x 128 x 256B
#define PS_O 196608                   // P: 2 groups x 64 x 256B
#define PBUF 16384
#define AL_O 229376                   // alpha[128]
#define LI_O 229888                   // 1/l [128]
#define SMEM_FLASH 230400

__global__ __launch_bounds__(512, 1)
void flash_kernel(const float* __restrict__ Q, const float* __restrict__ K,
                  const float* __restrict__ V, float* __restrict__ AO)
{
    extern __shared__ char smem[];
    uint32_t sb = smem_to_u32(smem);
    int t = threadIdx.x;
    int wid = t >> 5, lane = t & 31;
    int q0 = blockIdx.x * 128;
    int bh = blockIdx.y;
    const char* Qg = (const char*)(Q + (size_t)bh * 131072);
    const char* Kg = (const char*)(K + (size_t)bh * 131072);
    const char* Vg = (const char*)(V + (size_t)bh * 131072);

    int g = wid >> 3, w = wid & 7;
    int wql = (w & 1) * 32;
    int wkl = (w >> 1) * 16;
    int wdl = (w >> 1) * 32;

    #pragma unroll
    for (int it = 0; it < 8; ++it) {
        int idx = t + it * 512;
        int r = idx >> 5, sg = (idx & 31) * 16;
        cp16(sb + QS_O + (((uint32_t)r * 512 + sg) ^ ((r & 7) << 4)),
             Qg + (size_t)(q0 + r) * 512 + sg);
    }
    #pragma unroll
    for (int it = 0; it < 4; ++it) {
        int idx = t + it * 512;
        int r = idx >> 5, sg = (idx & 31) * 16;
        cp16(sb + KS_O + (((uint32_t)r * 512 + sg) ^ ((r & 7) << 4)),
             Kg + (size_t)r * 512 + sg);
        int rv = idx >> 4, sgv = (idx & 15) * 16;
        cp16(sb + VS_O + (((uint32_t)rv * 256 + sgv) ^ ((rv & 7) << 4)),
             Vg + (size_t)rv * 4096 + sgv);
    }
    CP_COMMIT();

    uint32_t rx = (uint32_t)(lane & 7) << 4;
    int arow = (lane & 7) + ((lane >> 3) & 1) * 8;
    int aseg = ((lane >> 4) & 1) * 16;
    int brow = (lane & 7) + ((lane >> 4) & 1) * 8;
    int bseg = ((lane >> 3) & 1) * 16;
    uint32_t aQ = sb + QS_O + (uint32_t)(g * 64 + wql + arow) * 512 + aseg;
    uint32_t bK = (uint32_t)(wkl + brow) * 512 + bseg;
    uint32_t aP = sb + PS_O + g * PBUF + (uint32_t)(wql + arow) * 256 + aseg;
    uint32_t bV = (uint32_t)(wdl + brow) * 256 + bseg;

    float oacc[2][4][4];
    #pragma unroll
    for (int i = 0; i < 2; ++i)
        #pragma unroll
        for (int j = 0; j < 4; ++j)
            #pragma unroll
            for (int c = 0; c < 4; ++c) oacc[i][j][c] = 0.f;

    float m_run = -1e30f, l_run = 0.f;
    float* al = (float*)(smem + AL_O);
    float* li = (float*)(smem + LI_O);
    int r_loc = (t & 255) >> 2;
    int qd = t & 3;
    int gr = t >> 2;
    const float scale = 0.08838834764831844f;

    for (int i = 0; i < 16; ++i) {
        __syncthreads();
        if (i + 1 < 16) {
            uint32_t kb = sb + KS_O + ((i + 1) & 1) * 32768;
            uint32_t vb = sb + VS_O + ((i + 1) & 1) * 32768;
            #pragma unroll
            for (int it = 0; it < 4; ++it) {
                int idx = t + it * 512;
                int r = idx >> 5, sg = (idx & 31) * 16;
                cp16(kb + (((uint32_t)r * 512 + sg) ^ ((r & 7) << 4)),
                     Kg + (size_t)((i + 1) * 64 + r) * 512 + sg);
                int rv = idx >> 4, sgv = (idx & 15) * 16;
                cp16(vb + (((uint32_t)rv * 256 + sgv) ^ ((rv & 7) << 4)),
                     Vg + (size_t)rv * 4096 + (size_t)(i + 1) * 256 + sgv);
            }
            CP_COMMIT();
            CP_WAIT(1);
        } else {
            CP_WAIT(0);
        }
        __syncthreads();

        float sacc[2][2][4];
        #pragma unroll
        for (int a = 0; a < 2; ++a)
            #pragma unroll
            for (int b = 0; b < 2; ++b)
                #pragma unroll
                for (int c = 0; c < 4; ++c) sacc[a][b][c] = 0.f;

        uint32_t kb = sb + KS_O + (i & 1) * 32768 + bK;
        #pragma unroll
        for (int d8 = 0; d8 < 16; ++d8) {
            uint32_t ko = d8 * 32;
            uint32_t a0[4], a1[4], bb[4];
            ldsm4(a0, (aQ + ko) ^ rx);
            ldsm4(a1, (aQ + 16 * 512 + ko) ^ rx);
            ldsm4(bb, (kb + ko) ^ rx);
            mma_tf32(sacc[0][0], a0, bb[0], bb[1]);
            mma_tf32(sacc[0][1], a0, bb[2], bb[3]);
            mma_tf32(sacc[1][0], a1, bb[0], bb[1]);
            mma_tf32(sacc[1][1], a1, bb[2], bb[3]);
        }

        {
            int lr2 = lane >> 2, lc2 = (lane & 3) * 2;
            #pragma unroll
            for (int mt = 0; mt < 2; ++mt) {
                int rr = wql + mt * 16 + lr2;
                uint32_t rxs = ((uint32_t)(rr & 7) << 4);
                #pragma unroll
                for (int nt = 0; nt < 2; ++nt) {
                    int cc = wkl + nt * 8 + lc2;
                    uint32_t o0 = ((uint32_t)(PS_O + g * PBUF + rr * 256 + cc * 4)) ^ rxs;
                    uint32_t o1 = ((uint32_t)(PS_O + g * PBUF + (rr + 8) * 256 + cc * 4)) ^ rxs;
                    *(float2*)(smem + o0) = make_float2(sacc[mt][nt][0], sacc[mt][nt][1]);
                    *(float2*)(smem + o1) = make_float2(sacc[mt][nt][2], sacc[mt][nt][3]);
                }
            }
        }
        GROUP_BAR(g + 1);

        {
            uint32_t rxs = ((uint32_t)(r_loc & 7) << 4);
            uint32_t pbase = (uint32_t)(PS_O + g * PBUF + r_loc * 256 + qd * 64);
            float4 vv[4];
            float mx = -1e30f;
            #pragma unroll
            for (int j = 0; j < 4; ++j) {
                vv[j] = *(float4*)(smem + ((pbase + j * 16) ^ rxs));
                vv[j].x *= scale; vv[j].y *= scale;
                vv[j].z *= scale; vv[j].w *= scale;
                mx = fmaxf(mx, fmaxf(fmaxf(vv[j].x, vv[j].y),
                                     fmaxf(vv[j].z, vv[j].w)));
            }
            mx = fmaxf(mx, __shfl_xor_sync(~0u, mx, 1));
            mx = fmaxf(mx, __shfl_xor_sync(~0u, mx, 2));
            float m_new = fmaxf(m_run, mx);
            float sum = 0.f;
            #pragma unroll
            for (int j = 0; j < 4; ++j) {
                float4 e;
                e.x = __expf(vv[j].x - m_new); e.y = __expf(vv[j].y - m_new);
                e.z = __expf(vv[j].z - m_new); e.w = __expf(vv[j].w - m_new);
                sum += e.x + e.y + e.z + e.w;
                e.x = to_tf32(e.x); e.y = to_tf32(e.y);
                e.z = to_tf32(e.z); e.w = to_tf32(e.w);
                *(float4*)(smem + ((pbase + j * 16) ^ rxs)) = e;
            }
            sum += __shfl_xor_sync(~0u, sum, 1);
            sum += __shfl_xor_sync(~0u, sum, 2);
            float alpha = __expf(m_run - m_new);
            l_run = l_run * alpha + sum;
            m_run = m_new;
            if (qd == 0) al[gr] = alpha;
        }
        GROUP_BAR(g + 1);

        #pragma unroll
        for (int mt = 0; mt < 2; ++mt) {
            int rr = wql + mt * 16 + (lane >> 2);
            float a0 = al[g * 64 + rr], a1 = al[g * 64 + rr + 8];
            #pragma unroll
            for (int nt = 0; nt < 4; ++nt) {
                oacc[mt][nt][0] *= a0; oacc[mt][nt][1] *= a0;
                oacc[mt][nt][2] *= a1; oacc[mt][nt][3] *= a1;
            }
        }
        uint32_t vb = sb + VS_O + (i & 1) * 32768 + bV;
        #pragma unroll
        for (int k8 = 0; k8 < 8; ++k8) {
            uint32_t ko = k8 * 32;
            uint32_t a0[4], a1[4];
            ldsm4(a0, (aP + ko) ^ rx);
            ldsm4(a1, (aP + 16 * 256 + ko) ^ rx);
            #pragma unroll
            for (int np = 0; np < 2; ++np) {
                uint32_t bb[4];
                ldsm4(bb, (vb + np * 16 * 256 + ko) ^ rx);
                mma_tf32(oacc[0][2*np    ], a0, bb[0], bb[1]);
                mma_tf32(oacc[0][2*np + 1], a0, bb[2], bb[3]);
                mma_tf32(oacc[1][2*np    ], a1, bb[0], bb[1]);
                mma_tf32(oacc[1][2*np + 1], a1, bb[2], bb[3]);
            }
        }
    }

    if (qd == 0) li[gr] = 1.f / l_run;
    __syncthreads();

    float* st = (float*)smem;
    #pragma unroll
    for (int mt = 0; mt < 2; ++mt) {
        int rr = wql + mt * 16 + (lane >> 2);
        int grr = g * 64 + rr;
        float li0 = li[grr], li1 = li[grr + 8];
        #pragma unroll
        for (int nt = 0; nt < 4; ++nt) {
            int cc = wdl + nt * 8 + (lane & 3) * 2;
            st[grr * 132 + cc]           = oacc[mt][nt][0] * li0;
            st[grr * 132 + cc + 1]       = oacc[mt][nt][1] * li0;
            st[(grr + 8) * 132 + cc]     = oacc[mt][nt][2] * li1;
            st[(grr + 8) * 132 + cc + 1] = oacc[mt][nt][3] * li1;
        }
    }
    __syncthreads();

    float* aob = AO + (size_t)(bh >> 2) * 524288 + (size_t)(bh & 3) * 128;
    for (int idx = t; idx < 4096; idx += 512) {
        int m = idx >> 5, c4 = (idx & 31) * 4;
        float4 v = *(const float4*)(st + m * 132 + c4);
        v.x = to_tf32(v.x); v.y = to_tf32(v.y);
        v.z = to_tf32(v.z); v.w = to_tf32(v.w);
        *(float4*)(aob + (size_t)(q0 + m) * 512 + c4) = v;
    }
}

// ==================== launch ================================================
extern "C" void kernel_launch(void* const* d_in, const int* in_sizes, int n_in,
                              void* d_out, int out_size)
{
    const float* x     = (const float*)d_in[0];
    const float* gamma = (const float*)d_in[1];
    const float* beta  = (const float*)d_in[2];
    const float* wq    = (const float*)d_in[3];
    const float* bq    = (const float*)d_in[4];
    const float* wk    = (const float*)d_in[5];
    const float* bk    = (const float*)d_in[6];
    const float* wv    = (const float*)d_in[7];
    const float* bv    = (const float*)d_in[8];
    const float* wp    = (const float*)d_in[9];
    const float* bp    = (const float*)d_in[10];
    float* out = (float*)d_out;

    float *hnT, *W, *q, *k, *v, *ao;
    cudaGetSymbolAddress((void**)&hnT, g_hnT);
    cudaGetSymbolAddress((void**)&W,   g_w);
    cudaGetSymbolAddress((void**)&q,   g_q);
    cudaGetSymbolAddress((void**)&k,   g_k);
    cudaGetSymbolAddress((void**)&v,   g_v);
    cudaGetSymbolAddress((void**)&ao,  g_ao);

    cudaFuncSetAttribute(gn_fused,  cudaFuncAttributeMaxDynamicSharedMemorySize, GN_SMEM);
    cudaFuncSetAttribute(gemm_tf<1>, cudaFuncAttributeMaxDynamicSharedMemorySize, SMEM_GEMM);
    cudaFuncSetAttribute(gemm_tf<4>, cudaFuncAttributeMaxDynamicSharedMemorySize, SMEM_GEMM);
    cudaFuncSetAttribute(gemm_tf<5>, cudaFuncAttributeMaxDynamicSharedMemorySize, SMEM_GEMM);
    cudaFuncSetAttribute(flash_kernel, cudaFuncAttributeMaxDynamicSharedMemorySize, SMEM_FLASH);

    gn_fused<<<BATCH * NGRP, 512, GN_SMEM>>>(x, gamma, beta, hnT);
    wconv_kernel<<<dim3(1024, 4), 256>>>(wq, wk, wv, wp, W);

    const long long HNB = (long long)HWSZ * CCH;     // 524288
    const long long WS  = (long long)CCH * CCH;      // 262144

    // fused Q+K conv: N=1024 over packed [wq; wk]
    gemm_tf<5><<<dim3(8, 8, BATCH), 256, SMEM_GEMM>>>(
        hnT, HNB, W, 0, CCH, bq, bk, nullptr, q, k);
    // V conv: M=o, N=p
    gemm_tf<1><<<dim3(8, 4, BATCH), 256, SMEM_GEMM>>>(
        W + 2 * WS, 0, hnT, HNB, CCH, bv, nullptr, nullptr, v, nullptr);
    // fused attention -> ao [b][p][c]
    flash_kernel<<<dim3(8, 64), 512, SMEM_FLASH>>>(q, k, v, ao);
    // proj + bias + residual -> out [b][o][p]
    gemm_tf<4><<<dim3(4, 8, BATCH), 256, SMEM_GEMM>>>(
        ao, HNB, W + 3 * WS, 0, CCH, bp, nullptr, x, out, nullptr);
}

// round 17
// speedup vs baseline: 1.0732x; 1.0197x over previous
#include <cuda_runtime.h>
#include <cstdint>

#define BATCH 16
#define CCH   512
#define HWSZ  1024
#define NHEAD 4
#define HDIM  128
#define NGRP  32
#define CPG   16
#define EPSV  1e-5f

// ======================= PTX helpers ========================================
__device__ __forceinline__ uint32_t smem_to_u32(const void* p) {
    uint32_t a;
    asm("{ .reg .u64 t; cvta.to.shared.u64 t, %1; cvt.u32.u64 %0, t; }"
        : "=r"(a) : "l"(p));
    return a;
}
__device__ __forceinline__ void cp16(uint32_t dst, const void* src) {
    asm volatile("cp.async.cg.shared.global [%0], [%1], 16;"
                 :: "r"(dst), "l"(src));
}
#define CP_COMMIT() asm volatile("cp.async.commit_group;" ::: "memory")
#define CP_WAIT(n)  asm volatile("cp.async.wait_group %0;" :: "n"(n) : "memory")

__device__ __forceinline__ void ldsm4(uint32_t* r, uint32_t addr) {
    asm volatile("ldmatrix.sync.aligned.m8n8.x4.shared.b16 {%0,%1,%2,%3}, [%4];"
                 : "=r"(r[0]), "=r"(r[1]), "=r"(r[2]), "=r"(r[3]) : "r"(addr));
}
__device__ __forceinline__ void mma_tf32(float* c, const uint32_t* a,
                                         uint32_t b0, uint32_t b1) {
    asm volatile(
        "mma.sync.aligned.m16n8k8.row.col.f32.tf32.tf32.f32 "
        "{%0,%1,%2,%3}, {%4,%5,%6,%7}, {%8,%9}, {%0,%1,%2,%3};"
        : "+f"(c[0]), "+f"(c[1]), "+f"(c[2]), "+f"(c[3])
        : "r"(a[0]), "r"(a[1]), "r"(a[2]), "r"(a[3]), "r"(b0), "r"(b1));
}
__device__ __forceinline__ float to_tf32(float x) {
    uint32_t u;
    asm("cvt.rna.tf32.f32 %0, %1;" : "=r"(u) : "f"(x));
    return __uint_as_float(u);
}

// ========================= scratch (static) ================================
__device__ float g_hnT[BATCH * HWSZ * CCH];              // tf32 [b][p][c]
__device__ float g_w  [4 * CCH * CCH];                   // tf32 weights [o][c]
__device__ float g_q  [BATCH * NHEAD * HWSZ * HDIM];     // [bh][p][d]
__device__ float g_k  [BATCH * NHEAD * HWSZ * HDIM];     // [bh][p][d]
__device__ float g_v  [BATCH * NHEAD * HDIM * HWSZ];     // [bh][d][p]
__device__ float g_ao [BATCH * HWSZ * CCH];              // tf32 [b][p][c]

// ======== fused GroupNorm: stats + normalize + transpose + tf32 ============
#define GN_SMEM (65536 + 512)
__global__ __launch_bounds__(512)
void gn_fused(const float* __restrict__ x, const float* __restrict__ gamma,
              const float* __restrict__ beta, float* __restrict__ T)
{
    extern __shared__ float sm[];
    float* tile = sm;                 // [16][1024]
    float* red  = sm + 16384;
    int bid = blockIdx.x;             // b*32 + g
    int b = bid >> 5, g = bid & 31;
    int t = threadIdx.x;

    const float4* src = (const float4*)(x + (size_t)bid * 16384);
    float4* tile4 = (float4*)tile;
    float s = 0.f, ss = 0.f;
    #pragma unroll
    for (int i = 0; i < 8; ++i) {
        int idx = t + i * 512;
        float4 v = src[idx];
        tile4[idx] = v;
        s  += v.x + v.y + v.z + v.w;
        ss += v.x*v.x + v.y*v.y + v.z*v.z + v.w*v.w;
    }
    int lane = t & 31, wid = t >> 5;
    #pragma unroll
    for (int o = 16; o; o >>= 1) {
        s  += __shfl_xor_sync(~0u, s, o);
        ss += __shfl_xor_sync(~0u, ss, o);
    }
    if (lane == 0) { red[wid] = s; red[16 + wid] = ss; }
    __syncthreads();
    if (t == 0) {
        float ts = 0.f, tss = 0.f;
        #pragma unroll
        for (int i = 0; i < 16; ++i) { ts += red[i]; tss += red[16 + i]; }
        float mean = ts * (1.f / 16384.f);
        float var  = tss * (1.f / 16384.f) - mean * mean;
        red[32] = mean;
        red[33] = rsqrtf(var + EPSV);
    }
    __syncthreads();
    if (t < 16) {
        float mean = red[32], inv = red[33];
        float gm = gamma[g * 16 + t] * inv;
        red[34 + t] = gm;
        red[50 + t] = beta[g * 16 + t] - mean * gm;
    }
    __syncthreads();

    #pragma unroll
    for (int rep = 0; rep < 2; ++rep) {
        int p = t + rep * 512;
        float4 o[4];
        float* op = (float*)o;
        #pragma unroll
        for (int c = 0; c < 16; ++c)
            op[c] = to_tf32(tile[c * 1024 + p] * red[34 + c] + red[50 + c]);
        float4* dst = (float4*)(T + ((size_t)b * 1024 + p) * 512 + g * 16);
        dst[0] = o[0]; dst[1] = o[1]; dst[2] = o[2]; dst[3] = o[3];
    }
}

// ==================== weight tf32 round =====================================
__global__ __launch_bounds__(256)
void wconv_kernel(const float* __restrict__ W0, const float* __restrict__ W1,
                  const float* __restrict__ W2, const float* __restrict__ W3,
                  float* __restrict__ Wo)
{
    const float* W = blockIdx.y == 0 ? W0 : blockIdx.y == 1 ? W1 :
                     blockIdx.y == 2 ? W2 : W3;
    size_t i = (size_t)blockIdx.x * 256 + threadIdx.x;
    Wo[(size_t)blockIdx.y * (CCH * CCH) + i] = to_tf32(W[i]);
}

// ==================== TF32 GEMM, 3-stage ===================================
// D[128 m][128 n] = sum_K A[m][K]*B[n][K]. 8 warps 4(M)x2(N), warp 32x64.
// Modes:
//  4: proj — M=p, N=o; +bias[n]+resid; fp32 out [b][o][p] (transposed stage)
//  6: QKV  — y<8: QK (M=p, N in [0,1024) packed [wq;wk]); y>=8: V (M=o, N=p)
#define TSTRIDE  144
#define TILE_T   18432
#define STAGE_T  (2 * TILE_T)
#define SMEM_GEMM (3 * STAGE_T)      // 110592
#define WS 262144

__device__ __forceinline__ void load_chunk_t(
    const float* __restrict__ Ab, const float* __restrict__ Bb,
    int K, int m0, int n0, int kc, uint32_t bufb, int t)
{
    #pragma unroll
    for (int it = 0; it < 4; ++it) {
        int idx = t + it * 256;
        int r   = idx >> 3;
        int sg  = (idx & 7) * 16;
        uint32_t so = (uint32_t)r * TSTRIDE + sg;
        cp16(bufb + so, (const char*)(Ab + (size_t)(m0 + r) * K + kc) + sg);
        cp16(bufb + TILE_T + so, (const char*)(Bb + (size_t)(n0 + r) * K + kc) + sg);
    }
}

template <int MODE>
__global__ __launch_bounds__(256, 2)
void gemm_tf(const float* __restrict__ A, long long A_bs,
             const float* __restrict__ B,
             int K, const float* __restrict__ bias,
             const float* __restrict__ bias2,
             const float* __restrict__ bias3,
             const float* __restrict__ resid,
             float* __restrict__ O, float* __restrict__ O2,
             float* __restrict__ O3)
{
    extern __shared__ char smem[];
    uint32_t sbase = smem_to_u32(smem);
    int t = threadIdx.x;
    int wid = t >> 5, lane = t & 31;
    int n0 = blockIdx.x * 128, z = blockIdx.z;

    bool isV = (MODE == 6) && (blockIdx.y >= 8);
    int m0 = (isV ? (blockIdx.y - 8) : blockIdx.y) * 128;

    const float* Ab;
    const float* Bb;
    if (MODE == 6) {
        if (isV) { Ab = B + 2 * WS; Bb = A + (long long)z * A_bs; }
        else     { Ab = A + (long long)z * A_bs; Bb = B; }
    } else {
        Ab = A + (long long)z * A_bs;
        Bb = B;
    }

    int wm = wid & 3;
    int wn = wid >> 2;

    uint32_t aOff = (uint32_t)(wm * 32 + (lane & 7) + ((lane >> 3) & 1) * 8)
                    * TSTRIDE + ((lane >> 4) & 1) * 16;
    uint32_t bOff = (uint32_t)(wn * 64 + (lane & 7) + ((lane >> 4) & 1) * 8)
                    * TSTRIDE + ((lane >> 3) & 1) * 16 + TILE_T;

    float acc[2][8][4];
    #pragma unroll
    for (int i = 0; i < 2; ++i)
        #pragma unroll
        for (int j = 0; j < 8; ++j)
            #pragma unroll
            for (int c = 0; c < 4; ++c) acc[i][j][c] = 0.f;

    const int NC = K >> 5;

    load_chunk_t(Ab, Bb, K, m0, n0, 0, sbase, t);
    CP_COMMIT();
    load_chunk_t(Ab, Bb, K, m0, n0, 32, sbase + STAGE_T, t);
    CP_COMMIT();

    for (int i = 0; i < NC; ++i) {
        if (i + 1 < NC) { CP_WAIT(1); } else { CP_WAIT(0); }
        __syncthreads();
        if (i + 2 < NC) {
            load_chunk_t(Ab, Bb, K, m0, n0, (i + 2) * 32,
                         sbase + ((i + 2) % 3) * STAGE_T, t);
            CP_COMMIT();
        }

        uint32_t base = sbase + (i % 3) * STAGE_T;
        #pragma unroll
        for (int kst = 0; kst < 4; ++kst) {
            uint32_t ko = kst * 32;
            uint32_t a0[4], a1[4];
            ldsm4(a0, base + aOff + ko);
            ldsm4(a1, base + aOff + 16 * TSTRIDE + ko);
            #pragma unroll
            for (int np = 0; np < 4; ++np) {
                uint32_t bb[4];
                ldsm4(bb, base + bOff + np * 16 * TSTRIDE + ko);
                mma_tf32(acc[0][2*np    ], a0, bb[0], bb[1]);
                mma_tf32(acc[0][2*np + 1], a0, bb[2], bb[3]);
                mma_tf32(acc[1][2*np    ], a1, bb[0], bb[1]);
                mma_tf32(acc[1][2*np + 1], a1, bb[2], bb[3]);
            }
        }
    }
    __syncthreads();

    float* st = (float*)smem;
    #pragma unroll
    for (int mt = 0; mt < 2; ++mt) {
        int r = wm * 32 + mt * 16 + (lane >> 2);
        #pragma unroll
        for (int nt = 0; nt < 8; ++nt) {
            int c = wn * 64 + nt * 8 + (lane & 3) * 2;
            const float* a = acc[mt][nt];
            if (MODE == 4) {
                st[(c    ) * 132 + r    ] = a[0];
                st[(c + 1) * 132 + r    ] = a[1];
                st[(c    ) * 132 + r + 8] = a[2];
                st[(c + 1) * 132 + r + 8] = a[3];
            } else {
                st[(r    ) * 132 + c    ] = a[0];
                st[(r    ) * 132 + c + 1] = a[1];
                st[(r + 8) * 132 + c    ] = a[2];
                st[(r + 8) * 132 + c + 1] = a[3];
            }
        }
    }
    __syncthreads();

    if (MODE == 4) {
        for (int idx = t; idx < 4096; idx += 256) {
            int n = idx >> 5, m4 = (idx & 31) * 4;
            size_t a = (size_t)z * 524288 + (size_t)(n0 + n) * 1024 + m0 + m4;
            float bv = __ldg(bias + n0 + n);
            float4 v = *(const float4*)(st + n * 132 + m4);
            float4 rr = *(const float4*)(resid + a);
            v.x += bv + rr.x; v.y += bv + rr.y;
            v.z += bv + rr.z; v.w += bv + rr.w;
            *(float4*)(O + a) = v;
        }
    } else if (isV) {
        for (int idx = t; idx < 4096; idx += 256) {
            int m = idx >> 5, c4 = (idx & 31) * 4;
            float4 v = *(const float4*)(st + m * 132 + c4);
            float bv = __ldg(bias3 + m0 + m);
            v.x += bv; v.y += bv; v.z += bv; v.w += bv;
            v.x = to_tf32(v.x); v.y = to_tf32(v.y);
            v.z = to_tf32(v.z); v.w = to_tf32(v.w);
            size_t off = (size_t)z * 524288 + (size_t)(m0 + m) * 1024 + n0 + c4;
            *(float4*)(O3 + off) = v;
        }
    } else {
        const float* bs = bias;
        float* Od = O;
        int nn0 = n0;
        if (n0 >= 512) { bs = bias2; Od = O2; nn0 = n0 - 512; }
        for (int idx = t; idx < 4096; idx += 256) {
            int m = idx >> 5, c4 = (idx & 31) * 4;
            float4 v = *(const float4*)(st + m * 132 + c4);
            v.x += __ldg(bs + nn0 + c4);
            v.y += __ldg(bs + nn0 + c4 + 1);
            v.z += __ldg(bs + nn0 + c4 + 2);
            v.w += __ldg(bs + nn0 + c4 + 3);
            v.x = to_tf32(v.x); v.y = to_tf32(v.y);
            v.z = to_tf32(v.z); v.w = to_tf32(v.w);
            size_t off = (size_t)z * 524288 + (size_t)nn0 * 1024
                       + (size_t)(m0 + m) * 128 + c4;
            *(float4*)(Od + off) = v;
        }
    }
}

// ============ fused flash attention: q-tile 64, 256 thr, 2 CTA/SM ==========
// grid (16, 64) x-major: 16 same-bh CTAs co-resident -> K/V L2 reuse.
// 8 warps: wm = wid&1 (32 q rows), wk = wid>>1 (S: 16 k; PV: 32 d).
// Single-buffered K,V; V transfer overlapped behind S-GEMM (split wait).
#define F_QS 0                        // Q: 64 x 512B swizzled
#define F_KS 32768                    // K: 64 x 512B
#define F_VS 65536                    // V: 128 x 256B
#define F_PS 98304                    // P: 64 x 256B
#define F_AL 114688                   // alpha[64]
#define F_LI 114944                   // 1/l[64]
#define SMEM_FLASH 115200

__global__ __launch_bounds__(256, 2)
void flash_kernel(const float* __restrict__ Q, const float* __restrict__ K,
                  const float* __restrict__ V, float* __restrict__ AO)
{
    extern __shared__ char smem[];
    uint32_t sb = smem_to_u32(smem);
    int t = threadIdx.x;
    int wid = t >> 5, lane = t & 31;
    int q0 = blockIdx.x * 64;
    int bh = blockIdx.y;
    const char* Qg = (const char*)(Q + (size_t)bh * 131072);
    const char* Kg = (const char*)(K + (size_t)bh * 131072);
    const char* Vg = (const char*)(V + (size_t)bh * 131072);

    int wm = wid & 1, wk = wid >> 1;
    int wql = wm * 32;
    int wkl = wk * 16;
    int wdl = wk * 32;

    // Q load (committed together with K(0) below)
    #pragma unroll
    for (int it = 0; it < 8; ++it) {
        int idx = t + it * 256;               // 64 rows x 32 segs
        int r = idx >> 5, sg = (idx & 31) * 16;
        cp16(sb + F_QS + (((uint32_t)r * 512 + sg) ^ ((r & 7) << 4)),
             Qg + (size_t)(q0 + r) * 512 + sg);
    }

    uint32_t rx = (uint32_t)(lane & 7) << 4;
    int arow = (lane & 7) + ((lane >> 3) & 1) * 8;
    int aseg = ((lane >> 4) & 1) * 16;
    int brow = (lane & 7) + ((lane >> 4) & 1) * 8;
    int bseg = ((lane >> 3) & 1) * 16;
    uint32_t aQ = sb + F_QS + (uint32_t)(wql + arow) * 512 + aseg;
    uint32_t kB = sb + F_KS + (uint32_t)(wkl + brow) * 512 + bseg;
    uint32_t aP = sb + F_PS + (uint32_t)(wql + arow) * 256 + aseg;
    uint32_t vB = sb + F_VS + (uint32_t)(wdl + brow) * 256 + bseg;

    float oacc[2][4][4];
    #pragma unroll
    for (int i = 0; i < 2; ++i)
        #pragma unroll
        for (int j = 0; j < 4; ++j)
            #pragma unroll
            for (int c = 0; c < 4; ++c) oacc[i][j][c] = 0.f;

    float m_run = -1e30f, l_run = 0.f;
    float* al = (float*)(smem + F_AL);
    float* li = (float*)(smem + F_LI);
    int r_loc = t >> 2;                // 0..63
    int qd = t & 3;
    const float scale = 0.08838834764831844f;

    for (int i = 0; i < 16; ++i) {
        __syncthreads();               // prev PV done; K/V buffers free
        // K(i) — grouped with Q on i==0
        #pragma unroll
        for (int it = 0; it < 8; ++it) {
            int idx = t + it * 256;
            int r = idx >> 5, sg = (idx & 31) * 16;
            cp16(sb + F_KS + (((uint32_t)r * 512 + sg) ^ ((r & 7) << 4)),
                 Kg + (size_t)(i * 64 + r) * 512 + sg);
        }
        CP_COMMIT();
        // V(i)
        #pragma unroll
        for (int it = 0; it < 8; ++it) {
            int idx = t + it * 256;
            int rv = idx >> 4, sgv = (idx & 15) * 16;
            cp16(sb + F_VS + (((uint32_t)rv * 256 + sgv) ^ ((rv & 7) << 4)),
                 Vg + (size_t)rv * 4096 + (size_t)i * 256 + sgv);
        }
        CP_COMMIT();
        CP_WAIT(1);                    // Q+K arrived
        __syncthreads();

        // ---- S = Q K^T ----
        float sacc[2][2][4];
        #pragma unroll
        for (int a = 0; a < 2; ++a)
            #pragma unroll
            for (int b = 0; b < 2; ++b)
                #pragma unroll
                for (int c = 0; c < 4; ++c) sacc[a][b][c] = 0.f;

        #pragma unroll
        for (int d8 = 0; d8 < 16; ++d8) {
            uint32_t ko = d8 * 32;
            uint32_t a0[4], a1[4], bb[4];
            ldsm4(a0, (aQ + ko) ^ rx);
            ldsm4(a1, (aQ + 16 * 512 + ko) ^ rx);
            ldsm4(bb, (kB + ko) ^ rx);
            mma_tf32(sacc[0][0], a0, bb[0], bb[1]);
            mma_tf32(sacc[0][1], a0, bb[2], bb[3]);
            mma_tf32(sacc[1][0], a1, bb[0], bb[1]);
            mma_tf32(sacc[1][1], a1, bb[2], bb[3]);
        }

        // ---- stage S to P (swizzled) ----
        {
            int lr2 = lane >> 2, lc2 = (lane & 3) * 2;
            #pragma unroll
            for (int mt = 0; mt < 2; ++mt) {
                int rr = wql + mt * 16 + lr2;
                uint32_t rxs = ((uint32_t)(rr & 7) << 4);
                #pragma unroll
                for (int nt = 0; nt < 2; ++nt) {
                    int cc = wkl + nt * 8 + lc2;
                    uint32_t o0 = ((uint32_t)(F_PS + rr * 256 + cc * 4)) ^ rxs;
                    uint32_t o1 = ((uint32_t)(F_PS + (rr + 8) * 256 + cc * 4)) ^ rxs;
                    *(float2*)(smem + o0) = make_float2(sacc[mt][nt][0], sacc[mt][nt][1]);
                    *(float2*)(smem + o1) = make_float2(sacc[mt][nt][2], sacc[mt][nt][3]);
                }
            }
        }
        __syncthreads();

        // ---- online softmax ----
        {
            uint32_t rxs = ((uint32_t)(r_loc & 7) << 4);
            uint32_t pbase = (uint32_t)(F_PS + r_loc * 256 + qd * 64);
            float4 vv[4];
            float mx = -1e30f;
            #pragma unroll
            for (int j = 0; j < 4; ++j) {
                vv[j] = *(float4*)(smem + ((pbase + j * 16) ^ rxs));
                vv[j].x *= scale; vv[j].y *= scale;
                vv[j].z *= scale; vv[j].w *= scale;
                mx = fmaxf(mx, fmaxf(fmaxf(vv[j].x, vv[j].y),
                                     fmaxf(vv[j].z, vv[j].w)));
            }
            mx = fmaxf(mx, __shfl_xor_sync(~0u, mx, 1));
            mx = fmaxf(mx, __shfl_xor_sync(~0u, mx, 2));
            float m_new = fmaxf(m_run, mx);
            float sum = 0.f;
            #pragma unroll
            for (int j = 0; j < 4; ++j) {
                float4 e;
                e.x = __expf(vv[j].x - m_new); e.y = __expf(vv[j].y - m_new);
                e.z = __expf(vv[j].z - m_new); e.w = __expf(vv[j].w - m_new);
                sum += e.x + e.y + e.z + e.w;
                e.x = to_tf32(e.x); e.y = to_tf32(e.y);
                e.z = to_tf32(e.z); e.w = to_tf32(e.w);
                *(float4*)(smem + ((pbase + j * 16) ^ rxs)) = e;
            }
            sum += __shfl_xor_sync(~0u, sum, 1);
            sum += __shfl_xor_sync(~0u, sum, 2);
            float alpha = __expf(m_run - m_new);
            l_run = l_run * alpha + sum;
            m_run = m_new;
            if (qd == 0) al[r_loc] = alpha;
        }
        CP_WAIT(0);                    // V arrived (overlapped with S+softmax)
        __syncthreads();

        // ---- rescale O, then O += P V ----
        #pragma unroll
        for (int mt = 0; mt < 2; ++mt) {
            int rr = wql + mt * 16 + (lane >> 2);
            float a0 = al[rr], a1 = al[rr + 8];
            #pragma unroll
            for (int nt = 0; nt < 4; ++nt) {
                oacc[mt][nt][0] *= a0; oacc[mt][nt][1] *= a0;
                oacc[mt][nt][2] *= a1; oacc[mt][nt][3] *= a1;
            }
        }
        #pragma unroll
        for (int k8 = 0; k8 < 8; ++k8) {
            uint32_t ko = k8 * 32;
            uint32_t a0[4], a1[4];
            ldsm4(a0, (aP + ko) ^ rx);
            ldsm4(a1, (aP + 16 * 256 + ko) ^ rx);
            #pragma unroll
            for (int np = 0; np < 2; ++np) {
                uint32_t bb[4];
                ldsm4(bb, (vB + np * 16 * 256 + ko) ^ rx);
                mma_tf32(oacc[0][2*np    ], a0, bb[0], bb[1]);
                mma_tf32(oacc[0][2*np + 1], a0, bb[2], bb[3]);
                mma_tf32(oacc[1][2*np    ], a1, bb[0], bb[1]);
                mma_tf32(oacc[1][2*np + 1], a1, bb[2], bb[3]);
            }
        }
    }

    // ---- finalize ----
    if (qd == 0) li[r_loc] = 1.f / l_run;
    __syncthreads();

    float* st = (float*)smem;          // 64x132 f32 over dead Q/K regions
    #pragma unroll
    for (int mt = 0; mt < 2; ++mt) {
        int rr = wql + mt * 16 + (lane >> 2);
        float li0 = li[rr], li1 = li[rr + 8];
        #pragma unroll
        for (int nt = 0; nt < 4; ++nt) {
            int cc = wdl + nt * 8 + (lane & 3) * 2;
            st[rr * 132 + cc]           = oacc[mt][nt][0] * li0;
            st[rr * 132 + cc + 1]       = oacc[mt][nt][1] * li0;
            st[(rr + 8) * 132 + cc]     = oacc[mt][nt][2] * li1;
            st[(rr + 8) * 132 + cc + 1] = oacc[mt][nt][3] * li1;
        }
    }
    __syncthreads();

    float* aob = AO + (size_t)(bh >> 2) * 524288 + (size_t)(bh & 3) * 128;
    for (int idx = t; idx < 2048; idx += 256) {
        int m = idx >> 5, c4 = (idx & 31) * 4;
        float4 v = *(const float4*)(st + m * 132 + c4);
        v.x = to_tf32(v.x); v.y = to_tf32(v.y);
        v.z = to_tf32(v.z); v.w = to_tf32(v.w);
        *(float4*)(aob + (size_t)(q0 + m) * 512 + c4) = v;
    }
}

// ==================== launch ================================================
extern "C" void kernel_launch(void* const* d_in, const int* in_sizes, int n_in,
                              void* d_out, int out_size)
{
    const float* x     = (const float*)d_in[0];
    const float* gamma = (const float*)d_in[1];
    const float* beta  = (const float*)d_in[2];
    const float* wq    = (const float*)d_in[3];
    const float* bq    = (const float*)d_in[4];
    const float* wk    = (const float*)d_in[5];
    const float* bk    = (const float*)d_in[6];
    const float* wv    = (const float*)d_in[7];
    const float* bv    = (const float*)d_in[8];
    const float* wp    = (const float*)d_in[9];
    const float* bp    = (const float*)d_in[10];
    float* out = (float*)d_out;

    float *hnT, *W, *q, *k, *v, *ao;
    cudaGetSymbolAddress((void**)&hnT, g_hnT);
    cudaGetSymbolAddress((void**)&W,   g_w);
    cudaGetSymbolAddress((void**)&q,   g_q);
    cudaGetSymbolAddress((void**)&k,   g_k);
    cudaGetSymbolAddress((void**)&v,   g_v);
    cudaGetSymbolAddress((void**)&ao,  g_ao);

    cudaFuncSetAttribute(gn_fused,  cudaFuncAttributeMaxDynamicSharedMemorySize, GN_SMEM);
    cudaFuncSetAttribute(gemm_tf<4>, cudaFuncAttributeMaxDynamicSharedMemorySize, SMEM_GEMM);
    cudaFuncSetAttribute(gemm_tf<6>, cudaFuncAttributeMaxDynamicSharedMemorySize, SMEM_GEMM);
    cudaFuncSetAttribute(flash_kernel, cudaFuncAttributeMaxDynamicSharedMemorySize, SMEM_FLASH);

    gn_fused<<<BATCH * NGRP, 512, GN_SMEM>>>(x, gamma, beta, hnT);
    wconv_kernel<<<dim3(1024, 4), 256>>>(wq, wk, wv, wp, W);

    const long long HNB = (long long)HWSZ * CCH;     // 524288

    // fused QKV conv: y<8 QK tiles, y>=8 V tiles
    gemm_tf<6><<<dim3(8, 12, BATCH), 256, SMEM_GEMM>>>(
        hnT, HNB, W, CCH, bq, bk, bv, nullptr, q, k, v);
    // fused attention -> ao [b][p][c]
    flash_kernel<<<dim3(16, 64), 256, SMEM_FLASH>>>(q, k, v, ao);
    // proj + bias + residual -> out [b][o][p]
    gemm_tf<4><<<dim3(4, 8, BATCH), 256, SMEM_GEMM>>>(
        ao, HNB, W + 3 * WS, CCH, bp, nullptr, nullptr, x, out, nullptr, nullptr);
}